// round 1
// baseline (speedup 1.0000x reference)
#include <cuda_runtime.h>
#include <math.h>

#define N_NODES 10000
#define F 256
#define E_POS 320000
#define E_TOT 330000
#define E_EVAL 100000
#define NEG_SLOPE 0.2f
#define EPS_F 1e-16f

// ---------------- scratch (device globals; allocation-free) ----------------
__device__ float g_bufA[N_NODES * F];
__device__ float g_bufB[N_NODES * F];
__device__ float g_bufC[N_NODES * F];
__device__ float g_als[N_NODES];
__device__ float g_ald[N_NODES];
__device__ int   g_deg[N_NODES];
__device__ int   g_off[N_NODES + 1];
__device__ int   g_cur[N_NODES];
__device__ int   g_srcs[E_TOT];

// ---------------- CSR build ----------------
__global__ void zero_deg_kernel() {
    int i = blockIdx.x * blockDim.x + threadIdx.x;
    if (i < N_NODES) g_deg[i] = 0;
}

__global__ void hist_kernel(const int* __restrict__ pos_ei) {
    int e = blockIdx.x * blockDim.x + threadIdx.x;
    if (e >= E_TOT) return;
    int dst = (e < E_POS) ? pos_ei[E_POS + e] : (e - E_POS);
    atomicAdd(&g_deg[dst], 1);
}

// single-block exclusive scan over 10000 degrees -> g_off, g_cur
__global__ void scan_kernel() {
    __shared__ int sh[1024];
    __shared__ int carry_sh;
    if (threadIdx.x == 0) carry_sh = 0;
    __syncthreads();
    for (int base = 0; base < 10240; base += 1024) {
        int i = base + (int)threadIdx.x;
        int v = (i < N_NODES) ? g_deg[i] : 0;
        sh[threadIdx.x] = v;
        __syncthreads();
        for (int o = 1; o < 1024; o <<= 1) {
            int t = (threadIdx.x >= (unsigned)o) ? sh[threadIdx.x - o] : 0;
            __syncthreads();
            sh[threadIdx.x] += t;
            __syncthreads();
        }
        int incl = sh[threadIdx.x];
        int carry = carry_sh;
        int excl = incl - v + carry;
        if (i < N_NODES) { g_off[i] = excl; g_cur[i] = excl; }
        if (i == N_NODES) g_off[N_NODES] = excl;
        __syncthreads();
        if (threadIdx.x == 1023) carry_sh = carry + sh[1023];
        __syncthreads();
    }
}

__global__ void scatter_kernel(const int* __restrict__ pos_ei) {
    int e = blockIdx.x * blockDim.x + threadIdx.x;
    if (e >= E_TOT) return;
    int src, dst;
    if (e < E_POS) { src = pos_ei[e]; dst = pos_ei[E_POS + e]; }
    else           { src = e - E_POS; dst = e - E_POS; }
    int pos = atomicAdd(&g_cur[dst], 1);
    g_srcs[pos] = src;
}

// ---------------- GEMM: C[M,256] = A[M,256] @ W[256,256] (+ bias) ----------------
// BM=64 BN=64 BK=32, 256 threads (16x16), 4x4 microtile
__global__ __launch_bounds__(256) void gemm_bias_kernel(
    const float* __restrict__ A, const float* __restrict__ W,
    const float* __restrict__ bias, float* __restrict__ C, int M) {
    __shared__ float As[32][64 + 4];
    __shared__ float Ws[32][64];
    const int tx = threadIdx.x % 16;
    const int ty = threadIdx.x / 16;
    const int row0 = blockIdx.y * 64;
    const int col0 = blockIdx.x * 64;
    float acc[4][4] = {};
    for (int k0 = 0; k0 < 256; k0 += 32) {
        // load A tile 64x32 (512 float4 / 256 threads = 2 each), store transposed
        #pragma unroll
        for (int it = 0; it < 2; it++) {
            int i = threadIdx.x + it * 256;     // 0..511
            int r = i >> 3;                     // row 0..63
            int kq = i & 7;                     // float4 index along K (0..7)
            float4 v = make_float4(0.f, 0.f, 0.f, 0.f);
            if (row0 + r < M)
                v = *reinterpret_cast<const float4*>(A + (size_t)(row0 + r) * 256 + k0 + kq * 4);
            As[kq * 4 + 0][r] = v.x;
            As[kq * 4 + 1][r] = v.y;
            As[kq * 4 + 2][r] = v.z;
            As[kq * 4 + 3][r] = v.w;
        }
        // load W tile 32x64 (512 float4 / 256 threads = 2 each)
        #pragma unroll
        for (int it = 0; it < 2; it++) {
            int i = threadIdx.x + it * 256;
            int r = i >> 4;                     // k row 0..31
            int cq = i & 15;                    // float4 along N
            float4 v = *reinterpret_cast<const float4*>(W + (size_t)(k0 + r) * 256 + col0 + cq * 4);
            *reinterpret_cast<float4*>(&Ws[r][cq * 4]) = v;
        }
        __syncthreads();
        #pragma unroll
        for (int kk = 0; kk < 32; kk++) {
            float a[4], b[4];
            #pragma unroll
            for (int i = 0; i < 4; i++) a[i] = As[kk][ty * 4 + i];
            #pragma unroll
            for (int j = 0; j < 4; j++) b[j] = Ws[kk][tx * 4 + j];
            #pragma unroll
            for (int i = 0; i < 4; i++)
                #pragma unroll
                for (int j = 0; j < 4; j++)
                    acc[i][j] = fmaf(a[i], b[j], acc[i][j]);
        }
        __syncthreads();
    }
    #pragma unroll
    for (int i = 0; i < 4; i++) {
        int r = row0 + ty * 4 + i;
        if (r >= M) continue;
        #pragma unroll
        for (int j = 0; j < 4; j++) {
            int c = col0 + tx * 4 + j;
            float v = acc[i][j];
            if (bias) v += bias[c];
            C[(size_t)r * 256 + c] = v;
        }
    }
}

// ---------------- attention logits per node ----------------
__global__ void compute_al_kernel(const float* __restrict__ hW,
                                  const float* __restrict__ a_src,
                                  const float* __restrict__ a_dst) {
    int warp = (blockIdx.x * blockDim.x + threadIdx.x) >> 5;
    int lane = threadIdx.x & 31;
    if (warp >= N_NODES) return;
    const float* hr = hW + (size_t)warp * F;
    float ss = 0.f, sd = 0.f;
    #pragma unroll
    for (int f = lane; f < F; f += 32) {
        float v = hr[f];
        ss = fmaf(v, a_src[f], ss);
        sd = fmaf(v, a_dst[f], sd);
    }
    #pragma unroll
    for (int o = 16; o > 0; o >>= 1) {
        ss += __shfl_xor_sync(0xffffffffu, ss, o);
        sd += __shfl_xor_sync(0xffffffffu, sd, o);
    }
    if (lane == 0) { g_als[warp] = ss; g_ald[warp] = sd; }
}

// ---------------- GAT aggregation: warp per destination node ----------------
__global__ void aggregate_kernel(const float* __restrict__ hW,
                                 const float* __restrict__ bias,
                                 float* __restrict__ out) {
    int node = (blockIdx.x * blockDim.x + threadIdx.x) >> 5;
    int lane = threadIdx.x & 31;
    if (node >= N_NODES) return;
    int beg = g_off[node], end = g_off[node + 1];
    float ald = g_ald[node];
    // pass 1: segment max
    float m = -INFINITY;
    for (int j = beg + lane; j < end; j += 32) {
        float e = g_als[g_srcs[j]] + ald;
        e = (e > 0.f) ? e : NEG_SLOPE * e;
        m = fmaxf(m, e);
    }
    #pragma unroll
    for (int o = 16; o > 0; o >>= 1) m = fmaxf(m, __shfl_xor_sync(0xffffffffu, m, o));
    // pass 2: sum of exp
    float s = 0.f;
    for (int j = beg + lane; j < end; j += 32) {
        float e = g_als[g_srcs[j]] + ald;
        e = (e > 0.f) ? e : NEG_SLOPE * e;
        s += __expf(e - m);
    }
    #pragma unroll
    for (int o = 16; o > 0; o >>= 1) s += __shfl_xor_sync(0xffffffffu, s, o);
    float inv = 1.f / (s + EPS_F);
    // pass 3: weighted feature gather (2 x LDG.128 per lane per neighbor)
    float4 acc0 = make_float4(0.f, 0.f, 0.f, 0.f);
    float4 acc1 = make_float4(0.f, 0.f, 0.f, 0.f);
    for (int j = beg; j < end; j++) {
        int src = g_srcs[j];                    // uniform across warp (broadcast)
        float e = g_als[src] + ald;
        e = (e > 0.f) ? e : NEG_SLOPE * e;
        float w = __expf(e - m);
        const float4* hr = reinterpret_cast<const float4*>(hW + (size_t)src * F);
        float4 v0 = __ldg(hr + lane);
        float4 v1 = __ldg(hr + lane + 32);
        acc0.x = fmaf(w, v0.x, acc0.x); acc0.y = fmaf(w, v0.y, acc0.y);
        acc0.z = fmaf(w, v0.z, acc0.z); acc0.w = fmaf(w, v0.w, acc0.w);
        acc1.x = fmaf(w, v1.x, acc1.x); acc1.y = fmaf(w, v1.y, acc1.y);
        acc1.z = fmaf(w, v1.z, acc1.z); acc1.w = fmaf(w, v1.w, acc1.w);
    }
    float4* orow = reinterpret_cast<float4*>(out + (size_t)node * F);
    const float4* brow = reinterpret_cast<const float4*>(bias);
    float4 b0 = __ldg(brow + lane);
    float4 b1 = __ldg(brow + lane + 32);
    float4 r0 = make_float4(acc0.x * inv + b0.x, acc0.y * inv + b0.y,
                            acc0.z * inv + b0.z, acc0.w * inv + b0.w);
    float4 r1 = make_float4(acc1.x * inv + b1.x, acc1.y * inv + b1.y,
                            acc1.z * inv + b1.z, acc1.w * inv + b1.w);
    orow[lane] = r0;
    orow[lane + 32] = r1;
}

// ---------------- eval-edge dot products ----------------
__global__ void dot_kernel(const float* __restrict__ h,
                           const int* __restrict__ ei,
                           float* __restrict__ out) {
    int eid = (blockIdx.x * blockDim.x + threadIdx.x) >> 5;
    int lane = threadIdx.x & 31;
    if (eid >= E_EVAL) return;
    int a = ei[eid];
    int b = ei[E_EVAL + eid];
    const float4* ha = reinterpret_cast<const float4*>(h + (size_t)a * F);
    const float4* hb = reinterpret_cast<const float4*>(h + (size_t)b * F);
    float s = 0.f;
    #pragma unroll
    for (int k = 0; k < 2; k++) {
        float4 va = __ldg(ha + lane + k * 32);
        float4 vb = __ldg(hb + lane + k * 32);
        s = fmaf(va.x, vb.x, s);
        s = fmaf(va.y, vb.y, s);
        s = fmaf(va.z, vb.z, s);
        s = fmaf(va.w, vb.w, s);
    }
    #pragma unroll
    for (int o = 16; o > 0; o >>= 1) s += __shfl_xor_sync(0xffffffffu, s, o);
    if (lane == 0) out[eid] = s;
}

// ---------------- launch ----------------
extern "C" void kernel_launch(void* const* d_in, const int* in_sizes, int n_in,
                              void* d_out, int out_size) {
    const float* x       = (const float*)d_in[0];
    const int*   pos_ei  = (const int*)  d_in[1];
    const int*   ev_ei   = (const int*)  d_in[2];
    const float* Win_W   = (const float*)d_in[3];
    const float* Win_b   = (const float*)d_in[4];
    const float* W1      = (const float*)d_in[5];
    const float* a1_src  = (const float*)d_in[6];
    const float* a1_dst  = (const float*)d_in[7];
    const float* b1      = (const float*)d_in[8];
    const float* W2      = (const float*)d_in[9];
    const float* a2_src  = (const float*)d_in[10];
    const float* a2_dst  = (const float*)d_in[11];
    const float* b2      = (const float*)d_in[12];
    float* out = (float*)d_out;

    float *pA, *pB, *pC;
    cudaGetSymbolAddress((void**)&pA, g_bufA);
    cudaGetSymbolAddress((void**)&pB, g_bufB);
    cudaGetSymbolAddress((void**)&pC, g_bufC);

    dim3 ggrid(4, (N_NODES + 63) / 64);

    // CSR build (independent of GEMMs)
    zero_deg_kernel<<<(N_NODES + 255) / 256, 256>>>();
    hist_kernel<<<(E_TOT + 255) / 256, 256>>>(pos_ei);
    scan_kernel<<<1, 1024>>>();
    scatter_kernel<<<(E_TOT + 255) / 256, 256>>>(pos_ei);

    // h0 = x @ Win_W + Win_b
    gemm_bias_kernel<<<ggrid, 256>>>(x, Win_W, Win_b, pA, N_NODES);

    const int warps_blocks_n = (N_NODES * 32 + 255) / 256;

    // ---- GAT layer 1 ----
    gemm_bias_kernel<<<ggrid, 256>>>(pA, W1, nullptr, pB, N_NODES);
    compute_al_kernel<<<warps_blocks_n, 256>>>(pB, a1_src, a1_dst);
    aggregate_kernel<<<warps_blocks_n, 256>>>(pB, b1, pC);

    // ---- GAT layer 2 ----
    gemm_bias_kernel<<<ggrid, 256>>>(pC, W2, nullptr, pB, N_NODES);
    compute_al_kernel<<<warps_blocks_n, 256>>>(pB, a2_src, a2_dst);
    aggregate_kernel<<<warps_blocks_n, 256>>>(pB, b2, pA);

    // ---- eval logits ----
    dot_kernel<<<(E_EVAL * 32 + 255) / 256, 256>>>(pA, ev_ei, out);
}

// round 3
// speedup vs baseline: 1.3101x; 1.3101x over previous
#include <cuda_runtime.h>
#include <cuda_bf16.h>
#include <cstdint>
#include <math.h>

#define N_NODES 10000
#define F 256
#define E_POS 320000
#define E_TOT 330000
#define E_EVAL 100000
#define NEG_SLOPE 0.2f
#define EPS_F 1e-16f
#define SLOT_CAP 128

// ---------------- scratch (device globals; allocation-free) ----------------
__device__ float g_bufA[N_NODES * F];
__device__ float g_bufB[N_NODES * F];
__device__ float g_bufC[N_NODES * F];
__device__ float g_als[N_NODES];
__device__ float g_ald[N_NODES];
__device__ int   g_deg[N_NODES];
__device__ int   g_srcs[N_NODES * SLOT_CAP];
__device__ __nv_bfloat16 g_Ah[N_NODES * F];
__device__ __nv_bfloat16 g_Al[N_NODES * F];
__device__ __nv_bfloat16 g_Bh[F * F];   // transposed: [n][k]
__device__ __nv_bfloat16 g_Bl[F * F];

#define SW128(o) ((o) ^ (((o) >> 3) & 0x70))

__device__ __forceinline__ uint32_t smem_to_u32(const void* p) {
    uint32_t a;
    asm("{ .reg .u64 t; cvta.to.shared.u64 t, %1; cvt.u32.u64 %0, t; }"
        : "=r"(a) : "l"(p));
    return a;
}
__device__ __forceinline__ void ldsm_x4(uint32_t* r, uint32_t addr) {
    asm volatile("ldmatrix.sync.aligned.m8n8.x4.shared.b16 {%0,%1,%2,%3}, [%4];"
        : "=r"(r[0]), "=r"(r[1]), "=r"(r[2]), "=r"(r[3]) : "r"(addr));
}
__device__ __forceinline__ void ldsm_x2(uint32_t* r, uint32_t addr) {
    asm volatile("ldmatrix.sync.aligned.m8n8.x2.shared.b16 {%0,%1}, [%2];"
        : "=r"(r[0]), "=r"(r[1]) : "r"(addr));
}
__device__ __forceinline__ void mma16816(float* c, const uint32_t* a, const uint32_t* b) {
    asm volatile(
        "mma.sync.aligned.m16n8k16.row.col.f32.bf16.bf16.f32 "
        "{%0,%1,%2,%3}, {%4,%5,%6,%7}, {%8,%9}, {%0,%1,%2,%3};"
        : "+f"(c[0]), "+f"(c[1]), "+f"(c[2]), "+f"(c[3])
        : "r"(a[0]), "r"(a[1]), "r"(a[2]), "r"(a[3]), "r"(b[0]), "r"(b[1]));
}

// ---------------- prep / CSR ----------------
__global__ void prep_kernel() {
    int i = blockIdx.x * blockDim.x + threadIdx.x;
    if (i < N_NODES) g_deg[i] = 0;
}
__global__ void scatter_kernel(const int* __restrict__ pos_ei) {
    int e = blockIdx.x * blockDim.x + threadIdx.x;
    if (e >= E_TOT) return;
    int src, dst;
    if (e < E_POS) { src = pos_ei[e]; dst = pos_ei[E_POS + e]; }
    else           { src = e - E_POS; dst = e - E_POS; }
    int pos = atomicAdd(&g_deg[dst], 1);
    if (pos < SLOT_CAP) g_srcs[dst * SLOT_CAP + pos] = src;
}

// ---------------- fp32 -> bf16 hi/lo split (A) + W split-transpose (B) ----------------
#define M4_A (N_NODES * F / 4)
__global__ void split_kernel(const float* __restrict__ A, const float* __restrict__ W) {
    int idx = blockIdx.x * blockDim.x + threadIdx.x;
    if (idx < M4_A) {
        float4 v = reinterpret_cast<const float4*>(A)[idx];
        __nv_bfloat16 h0 = __float2bfloat16(v.x), h1 = __float2bfloat16(v.y);
        __nv_bfloat16 h2 = __float2bfloat16(v.z), h3 = __float2bfloat16(v.w);
        __nv_bfloat16 l0 = __float2bfloat16(v.x - __bfloat162float(h0));
        __nv_bfloat16 l1 = __float2bfloat16(v.y - __bfloat162float(h1));
        __nv_bfloat16 l2 = __float2bfloat16(v.z - __bfloat162float(h2));
        __nv_bfloat16 l3 = __float2bfloat16(v.w - __bfloat162float(h3));
        __nv_bfloat162* ph = reinterpret_cast<__nv_bfloat162*>(g_Ah);
        __nv_bfloat162* pl = reinterpret_cast<__nv_bfloat162*>(g_Al);
        ph[idx * 2]     = __nv_bfloat162(h0, h1);
        ph[idx * 2 + 1] = __nv_bfloat162(h2, h3);
        pl[idx * 2]     = __nv_bfloat162(l0, l1);
        pl[idx * 2 + 1] = __nv_bfloat162(l2, l3);
    } else {
        int i = idx - M4_A;
        if (i < F * F) {
            int k = i >> 8, n = i & 255;
            float v = W[i];                 // W[k][n]
            __nv_bfloat16 h = __float2bfloat16(v);
            __nv_bfloat16 l = __float2bfloat16(v - __bfloat162float(h));
            g_Bh[n * F + k] = h;            // store transposed
            g_Bl[n * F + k] = l;
        }
    }
}

// ---------------- HMMA GEMM: out[M,256] = A @ W (+bias) ----------------
// BM=128 BN=128 BK=64, 8 warps (2m x 4n), warp tile 64x32, bf16-split 3 terms
#define SA_H 0
#define SA_L 16384
#define SB_H 32768
#define SB_L 49152
#define SMEM_MMA (65536 + 1024)

__global__ __launch_bounds__(256) void gemm_mma_kernel(
    const float* __restrict__ bias, float* __restrict__ out, int M) {
    extern __shared__ char dsmem[];
    const int tid = threadIdx.x;
    const int wid = tid >> 5;
    const int lane = tid & 31;
    const int wm = wid >> 2;          // 0..1
    const int wn = wid & 3;           // 0..3
    const int row0 = blockIdx.y * 128;
    const int col0 = blockIdx.x * 128;

    uint32_t dsb = smem_to_u32(dsmem);
    uint32_t sb = (dsb + 1023) & ~1023u;
    char* tiles = dsmem + (sb - dsb);

    float acc[4][4][4] = {};          // [mt][nt][4]

    // fragment addresses (depend only on lane / warp / ks)
    const int a_row = wm * 64 + (lane & 15);
    const int a_kb  = (lane >> 4) * 16;         // +8 bf16 for upper half-warp (bytes)
    const int b_row = wn * 32 + (lane & 7);
    const int b_kb  = ((lane >> 3) & 3 & 1) * 16; // lanes 8-15 -> k+8 (bytes)

    for (int c = 0; c < 4; c++) {     // K outer: 64 per iter
        // ---- load 4 tiles (128 rows x 64 bf16 each), SW128-swizzled ----
        const __nv_bfloat16* ops[4] = { g_Ah, g_Al, g_Bh, g_Bl };
        const int boff[4] = { SA_H, SA_L, SB_H, SB_L };
        #pragma unroll
        for (int t = 0; t < 4; t++) {
            int brow = (t < 2) ? row0 : col0;
            #pragma unroll
            for (int it = 0; it < 4; it++) {
                int i = tid + it * 256;           // 0..1023
                int r = i >> 3, j = i & 7;
                int grow = brow + r;
                uint4 v = make_uint4(0u, 0u, 0u, 0u);
                if (t >= 2 || grow < M)
                    v = *reinterpret_cast<const uint4*>(ops[t] + (size_t)grow * F + c * 64 + j * 8);
                uint32_t off = r * 128 + j * 16;
                *reinterpret_cast<uint4*>(tiles + boff[t] + SW128(off)) = v;
            }
        }
        __syncthreads();

        #pragma unroll
        for (int ks = 0; ks < 4; ks++) {
            uint32_t ah[4][4], al[4][4], bh[4][2], bl[4][2];
            #pragma unroll
            for (int mt = 0; mt < 4; mt++) {
                uint32_t off = SW128((uint32_t)((a_row + mt * 16) * 128 + ks * 32 + a_kb));
                ldsm_x4(ah[mt], sb + SA_H + off);
                ldsm_x4(al[mt], sb + SA_L + off);
            }
            #pragma unroll
            for (int nt = 0; nt < 4; nt++) {
                uint32_t off = SW128((uint32_t)((b_row + nt * 8) * 128 + ks * 32 + b_kb));
                ldsm_x2(bh[nt], sb + SB_H + off);
                ldsm_x2(bl[nt], sb + SB_L + off);
            }
            #pragma unroll
            for (int mt = 0; mt < 4; mt++)
                #pragma unroll
                for (int nt = 0; nt < 4; nt++) {
                    mma16816(acc[mt][nt], ah[mt], bh[nt]);
                    mma16816(acc[mt][nt], ah[mt], bl[nt]);
                    mma16816(acc[mt][nt], al[mt], bh[nt]);
                }
        }
        __syncthreads();
    }

    // ---- epilogue ----
    #pragma unroll
    for (int mt = 0; mt < 4; mt++) {
        #pragma unroll
        for (int half = 0; half < 2; half++) {
            int gr = row0 + wm * 64 + mt * 16 + (lane >> 2) + half * 8;
            if (gr >= M) continue;
            #pragma unroll
            for (int nt = 0; nt < 4; nt++) {
                int gc = col0 + wn * 32 + nt * 8 + (lane & 3) * 2;
                float v0 = acc[mt][nt][half * 2 + 0];
                float v1 = acc[mt][nt][half * 2 + 1];
                if (bias) { v0 += bias[gc]; v1 += bias[gc + 1]; }
                float2 vv = make_float2(v0, v1);
                *reinterpret_cast<float2*>(out + (size_t)gr * F + gc) = vv;
            }
        }
    }
}

// ---------------- attention logits per node ----------------
__global__ void compute_al_kernel(const float* __restrict__ hW,
                                  const float* __restrict__ a_src,
                                  const float* __restrict__ a_dst) {
    int warp = (blockIdx.x * blockDim.x + threadIdx.x) >> 5;
    int lane = threadIdx.x & 31;
    if (warp >= N_NODES) return;
    const float* hr = hW + (size_t)warp * F;
    float ss = 0.f, sd = 0.f;
    #pragma unroll
    for (int f = lane; f < F; f += 32) {
        float v = hr[f];
        ss = fmaf(v, a_src[f], ss);
        sd = fmaf(v, a_dst[f], sd);
    }
    #pragma unroll
    for (int o = 16; o > 0; o >>= 1) {
        ss += __shfl_xor_sync(0xffffffffu, ss, o);
        sd += __shfl_xor_sync(0xffffffffu, sd, o);
    }
    if (lane == 0) { g_als[warp] = ss; g_ald[warp] = sd; }
}

// ---------------- GAT aggregation: warp per destination node ----------------
__global__ void aggregate_kernel(const float* __restrict__ hW,
                                 const float* __restrict__ bias,
                                 float* __restrict__ out) {
    int node = (blockIdx.x * blockDim.x + threadIdx.x) >> 5;
    int lane = threadIdx.x & 31;
    if (node >= N_NODES) return;
    int beg = node * SLOT_CAP;
    int end = beg + g_deg[node];
    float ald = g_ald[node];
    float m = -INFINITY;
    for (int j = beg + lane; j < end; j += 32) {
        float e = g_als[g_srcs[j]] + ald;
        e = (e > 0.f) ? e : NEG_SLOPE * e;
        m = fmaxf(m, e);
    }
    #pragma unroll
    for (int o = 16; o > 0; o >>= 1) m = fmaxf(m, __shfl_xor_sync(0xffffffffu, m, o));
    float s = 0.f;
    for (int j = beg + lane; j < end; j += 32) {
        float e = g_als[g_srcs[j]] + ald;
        e = (e > 0.f) ? e : NEG_SLOPE * e;
        s += __expf(e - m);
    }
    #pragma unroll
    for (int o = 16; o > 0; o >>= 1) s += __shfl_xor_sync(0xffffffffu, s, o);
    float inv = 1.f / (s + EPS_F);
    float4 acc0 = make_float4(0.f, 0.f, 0.f, 0.f);
    float4 acc1 = make_float4(0.f, 0.f, 0.f, 0.f);
    for (int j = beg; j < end; j++) {
        int src = g_srcs[j];
        float e = g_als[src] + ald;
        e = (e > 0.f) ? e : NEG_SLOPE * e;
        float w = __expf(e - m);
        const float4* hr = reinterpret_cast<const float4*>(hW + (size_t)src * F);
        float4 v0 = __ldg(hr + lane);
        float4 v1 = __ldg(hr + lane + 32);
        acc0.x = fmaf(w, v0.x, acc0.x); acc0.y = fmaf(w, v0.y, acc0.y);
        acc0.z = fmaf(w, v0.z, acc0.z); acc0.w = fmaf(w, v0.w, acc0.w);
        acc1.x = fmaf(w, v1.x, acc1.x); acc1.y = fmaf(w, v1.y, acc1.y);
        acc1.z = fmaf(w, v1.z, acc1.z); acc1.w = fmaf(w, v1.w, acc1.w);
    }
    float4* orow = reinterpret_cast<float4*>(out + (size_t)node * F);
    const float4* brow = reinterpret_cast<const float4*>(bias);
    float4 b0 = __ldg(brow + lane);
    float4 b1 = __ldg(brow + lane + 32);
    orow[lane]      = make_float4(acc0.x * inv + b0.x, acc0.y * inv + b0.y,
                                  acc0.z * inv + b0.z, acc0.w * inv + b0.w);
    orow[lane + 32] = make_float4(acc1.x * inv + b1.x, acc1.y * inv + b1.y,
                                  acc1.z * inv + b1.z, acc1.w * inv + b1.w);
}

// ---------------- eval-edge dot products ----------------
__global__ void dot_kernel(const float* __restrict__ h,
                           const int* __restrict__ ei,
                           float* __restrict__ out) {
    int eid = (blockIdx.x * blockDim.x + threadIdx.x) >> 5;
    int lane = threadIdx.x & 31;
    if (eid >= E_EVAL) return;
    int a = ei[eid];
    int b = ei[E_EVAL + eid];
    const float4* ha = reinterpret_cast<const float4*>(h + (size_t)a * F);
    const float4* hb = reinterpret_cast<const float4*>(h + (size_t)b * F);
    float s = 0.f;
    #pragma unroll
    for (int k = 0; k < 2; k++) {
        float4 va = __ldg(ha + lane + k * 32);
        float4 vb = __ldg(hb + lane + k * 32);
        s = fmaf(va.x, vb.x, s);
        s = fmaf(va.y, vb.y, s);
        s = fmaf(va.z, vb.z, s);
        s = fmaf(va.w, vb.w, s);
    }
    #pragma unroll
    for (int o = 16; o > 0; o >>= 1) s += __shfl_xor_sync(0xffffffffu, s, o);
    if (lane == 0) out[eid] = s;
}

// ---------------- launch ----------------
extern "C" void kernel_launch(void* const* d_in, const int* in_sizes, int n_in,
                              void* d_out, int out_size) {
    const float* x       = (const float*)d_in[0];
    const int*   pos_ei  = (const int*)  d_in[1];
    const int*   ev_ei   = (const int*)  d_in[2];
    const float* Win_W   = (const float*)d_in[3];
    const float* Win_b   = (const float*)d_in[4];
    const float* W1      = (const float*)d_in[5];
    const float* a1_src  = (const float*)d_in[6];
    const float* a1_dst  = (const float*)d_in[7];
    const float* b1      = (const float*)d_in[8];
    const float* W2      = (const float*)d_in[9];
    const float* a2_src  = (const float*)d_in[10];
    const float* a2_dst  = (const float*)d_in[11];
    const float* b2      = (const float*)d_in[12];
    float* out = (float*)d_out;

    float *pA, *pB, *pC;
    cudaGetSymbolAddress((void**)&pA, g_bufA);
    cudaGetSymbolAddress((void**)&pB, g_bufB);
    cudaGetSymbolAddress((void**)&pC, g_bufC);

    cudaFuncSetAttribute(gemm_mma_kernel,
                         cudaFuncAttributeMaxDynamicSharedMemorySize, SMEM_MMA);

    const dim3 ggrid(2, (N_NODES + 127) / 128);
    const int split_blocks = (M4_A + F * F + 255) / 256;
    const int warps_blocks_n = (N_NODES * 32 + 255) / 256;

    prep_kernel<<<(N_NODES + 255) / 256, 256>>>();
    scatter_kernel<<<(E_TOT + 255) / 256, 256>>>(pos_ei);

    // h0 = x @ Win_W + Win_b
    split_kernel<<<split_blocks, 256>>>(x, Win_W);
    gemm_mma_kernel<<<ggrid, 256, SMEM_MMA>>>(Win_b, pA, N_NODES);

    // ---- GAT layer 1 ----
    split_kernel<<<split_blocks, 256>>>(pA, W1);
    gemm_mma_kernel<<<ggrid, 256, SMEM_MMA>>>(nullptr, pB, N_NODES);
    compute_al_kernel<<<warps_blocks_n, 256>>>(pB, a1_src, a1_dst);
    aggregate_kernel<<<warps_blocks_n, 256>>>(pB, b1, pC);

    // ---- GAT layer 2 ----
    split_kernel<<<split_blocks, 256>>>(pC, W2);
    gemm_mma_kernel<<<ggrid, 256, SMEM_MMA>>>(nullptr, pB, N_NODES);
    compute_al_kernel<<<warps_blocks_n, 256>>>(pB, a2_src, a2_dst);
    aggregate_kernel<<<warps_blocks_n, 256>>>(pB, b2, pA);

    // ---- eval logits ----
    dot_kernel<<<(E_EVAL * 32 + 255) / 256, 256>>>(pA, ev_ei, out);
}

// round 4
// speedup vs baseline: 1.5111x; 1.1534x over previous
#include <cuda_runtime.h>
#include <cuda_bf16.h>
#include <cstdint>
#include <math.h>

#define N_NODES 10000
#define F 256
#define E_POS 320000
#define E_TOT 330000
#define E_EVAL 100000
#define NEG_SLOPE 0.2f
#define EPS_F 1e-16f
#define SLOT_CAP 128

// ---------------- scratch (device globals; allocation-free) ----------------
__device__ float g_bufA[N_NODES * F];     // gemm fp32 out
__device__ float g_bufB[N_NODES * F];     // aggregate2 out (final h)
__device__ float g_als1[N_NODES];
__device__ float g_ald1[N_NODES];
__device__ float g_als2[N_NODES];
__device__ float g_ald2[N_NODES];
__device__ int   g_deg[N_NODES];
__device__ int   g_srcs[N_NODES * SLOT_CAP];
__device__ __nv_bfloat16 g_Ah[N_NODES * F];
__device__ __nv_bfloat16 g_Al[N_NODES * F];
__device__ __nv_bfloat16 g_Wh[3][F * F];  // transposed [n][k]
__device__ __nv_bfloat16 g_Wl[3][F * F];

#define SW128(o) ((o) ^ (((o) >> 3) & 0x70))

__device__ __forceinline__ uint32_t smem_to_u32(const void* p) {
    uint32_t a;
    asm("{ .reg .u64 t; cvta.to.shared.u64 t, %1; cvt.u32.u64 %0, t; }"
        : "=r"(a) : "l"(p));
    return a;
}
__device__ __forceinline__ void ldsm_x4(uint32_t* r, uint32_t addr) {
    asm volatile("ldmatrix.sync.aligned.m8n8.x4.shared.b16 {%0,%1,%2,%3}, [%4];"
        : "=r"(r[0]), "=r"(r[1]), "=r"(r[2]), "=r"(r[3]) : "r"(addr));
}
__device__ __forceinline__ void ldsm_x2(uint32_t* r, uint32_t addr) {
    asm volatile("ldmatrix.sync.aligned.m8n8.x2.shared.b16 {%0,%1}, [%2];"
        : "=r"(r[0]), "=r"(r[1]) : "r"(addr));
}
__device__ __forceinline__ void mma16816(float* c, const uint32_t* a, const uint32_t* b) {
    asm volatile(
        "mma.sync.aligned.m16n8k16.row.col.f32.bf16.bf16.f32 "
        "{%0,%1,%2,%3}, {%4,%5,%6,%7}, {%8,%9}, {%0,%1,%2,%3};"
        : "+f"(c[0]), "+f"(c[1]), "+f"(c[2]), "+f"(c[3])
        : "r"(a[0]), "r"(a[1]), "r"(a[2]), "r"(a[3]), "r"(b[0]), "r"(b[1]));
}
__device__ __forceinline__ void cp_async16(uint32_t saddr, const void* g, bool valid) {
    int sz = valid ? 16 : 0;
    asm volatile("cp.async.cg.shared.global [%0], [%1], 16, %2;"
        :: "r"(saddr), "l"(g), "r"(sz) : "memory");
}
#define CP_COMMIT() asm volatile("cp.async.commit_group;" ::: "memory")
#define CP_WAIT(n)  asm volatile("cp.async.wait_group %0;" :: "n"(n) : "memory")

// ---------------- prep / CSR ----------------
__global__ void prep_kernel() {
    int i = blockIdx.x * blockDim.x + threadIdx.x;
    if (i < N_NODES) {
        g_deg[i] = 0;
        g_als1[i] = 0.f; g_ald1[i] = 0.f;
        g_als2[i] = 0.f; g_ald2[i] = 0.f;
    }
}

#define E_Q (E_TOT / 4)   // 82500
__global__ void scatter_kernel(const int* __restrict__ pos_ei) {
    int gid = blockIdx.x * blockDim.x + threadIdx.x;
    if (gid >= E_Q) return;
    #pragma unroll
    for (int q = 0; q < 4; q++) {
        int e = gid + q * E_Q;
        int src, dst;
        if (e < E_POS) { src = __ldg(pos_ei + e); dst = __ldg(pos_ei + E_POS + e); }
        else           { src = e - E_POS; dst = src; }
        int pos = atomicAdd(&g_deg[dst], 1);
        if (pos < SLOT_CAP) g_srcs[dst * SLOT_CAP + pos] = src;
    }
}

// ---------------- split x + all 3 weight matrices ----------------
#define M4_A (N_NODES * F / 4)
__global__ void split_all_kernel(const float* __restrict__ x,
                                 const float* __restrict__ W0,
                                 const float* __restrict__ W1,
                                 const float* __restrict__ W2) {
    int idx = blockIdx.x * blockDim.x + threadIdx.x;
    if (idx < M4_A) {
        float4 v = reinterpret_cast<const float4*>(x)[idx];
        __nv_bfloat16 h0 = __float2bfloat16(v.x), h1 = __float2bfloat16(v.y);
        __nv_bfloat16 h2 = __float2bfloat16(v.z), h3 = __float2bfloat16(v.w);
        __nv_bfloat16 l0 = __float2bfloat16(v.x - __bfloat162float(h0));
        __nv_bfloat16 l1 = __float2bfloat16(v.y - __bfloat162float(h1));
        __nv_bfloat16 l2 = __float2bfloat16(v.z - __bfloat162float(h2));
        __nv_bfloat16 l3 = __float2bfloat16(v.w - __bfloat162float(h3));
        __nv_bfloat162* ph = reinterpret_cast<__nv_bfloat162*>(g_Ah);
        __nv_bfloat162* pl = reinterpret_cast<__nv_bfloat162*>(g_Al);
        ph[idx * 2]     = __nv_bfloat162(h0, h1);
        ph[idx * 2 + 1] = __nv_bfloat162(h2, h3);
        pl[idx * 2]     = __nv_bfloat162(l0, l1);
        pl[idx * 2 + 1] = __nv_bfloat162(l2, l3);
    } else {
        int i2 = idx - M4_A;
        if (i2 < 3 * F * F) {
            int w = i2 >> 16;
            int j = i2 & 65535;
            int k = j >> 8, n = j & 255;
            const float* W = (w == 0) ? W0 : (w == 1) ? W1 : W2;
            float v = __ldg(W + j);     // W[k][n]
            __nv_bfloat16 h = __float2bfloat16(v);
            __nv_bfloat16 l = __float2bfloat16(v - __bfloat162float(h));
            g_Wh[w][n * F + k] = h;     // transposed
            g_Wl[w][n * F + k] = l;
        }
    }
}

// ---------------- pipelined HMMA GEMM ----------------
#define SA_H 0
#define SA_L 16384
#define SB_H 32768
#define SB_L 49152
#define STAGE_BYTES 65536
#define SMEM_MMA (2 * STAGE_BYTES + 1024)

__global__ __launch_bounds__(256) void gemm_mma_kernel(
    const __nv_bfloat16* __restrict__ Bh, const __nv_bfloat16* __restrict__ Bl,
    const float* __restrict__ bias,
    const float* __restrict__ a_src, const float* __restrict__ a_dst,
    float* __restrict__ als, float* __restrict__ ald,
    float* __restrict__ out, int write_split, int M) {
    extern __shared__ char dsmem[];
    const int tid = threadIdx.x;
    const int wid = tid >> 5;
    const int lane = tid & 31;
    const int wm = wid >> 2;
    const int wn = wid & 3;
    const int row0 = blockIdx.y * 128;
    const int col0 = blockIdx.x * 128;

    uint32_t dsb = smem_to_u32(dsmem);
    uint32_t sb = (dsb + 1023) & ~1023u;

    float acc[4][4][4] = {};

    const int a_row = wm * 64 + (lane & 15);
    const int a_kb  = (lane >> 4) * 16;
    const int b_row = wn * 32 + (lane & 7);
    const int b_kb  = ((lane >> 3) & 1) * 16;

    const __nv_bfloat16* opsA[2] = { g_Ah, g_Al };
    const __nv_bfloat16* opsB[2] = { Bh, Bl };
    const int boffA[2] = { SA_H, SA_L };
    const int boffB[2] = { SB_H, SB_L };

    const int lr = tid >> 3;          // 0..31 row base per thread (with it*32)
    const int lj = tid & 7;           // 16B chunk

    #define LOAD_STAGE(cc, ss) do {                                              \
        uint32_t stb = sb + (ss) * STAGE_BYTES;                                   \
        _Pragma("unroll")                                                         \
        for (int t = 0; t < 2; t++) {                                             \
            _Pragma("unroll")                                                     \
            for (int it = 0; it < 4; it++) {                                      \
                int r = lr + it * 32;                                             \
                int grow = row0 + r;                                              \
                uint32_t off = SW128((uint32_t)(r * 128 + lj * 16));              \
                cp_async16(stb + boffA[t] + off,                                  \
                           opsA[t] + (size_t)grow * F + (cc) * 64 + lj * 8,       \
                           grow < M);                                             \
            }                                                                     \
        }                                                                         \
        _Pragma("unroll")                                                         \
        for (int t = 0; t < 2; t++) {                                             \
            _Pragma("unroll")                                                     \
            for (int it = 0; it < 4; it++) {                                      \
                int r = lr + it * 32;                                             \
                uint32_t off = SW128((uint32_t)(r * 128 + lj * 16));              \
                cp_async16(stb + boffB[t] + off,                                  \
                           opsB[t] + (size_t)(col0 + r) * F + (cc) * 64 + lj * 8, \
                           true);                                                 \
            }                                                                     \
        }                                                                         \
        CP_COMMIT();                                                              \
    } while (0)

    LOAD_STAGE(0, 0);

    #pragma unroll
    for (int c = 0; c < 4; c++) {
        if (c + 1 < 4) {
            LOAD_STAGE(c + 1, (c + 1) & 1);
            CP_WAIT(1);
        } else {
            CP_WAIT(0);
        }
        __syncthreads();
        uint32_t stb = sb + (c & 1) * STAGE_BYTES;
        #pragma unroll
        for (int ks = 0; ks < 4; ks++) {
            uint32_t ah[4][4], al[4][4], bh[4][2], bl[4][2];
            #pragma unroll
            for (int mt = 0; mt < 4; mt++) {
                uint32_t off = SW128((uint32_t)((a_row + mt * 16) * 128 + ks * 32 + a_kb));
                ldsm_x4(ah[mt], stb + SA_H + off);
                ldsm_x4(al[mt], stb + SA_L + off);
            }
            #pragma unroll
            for (int nt = 0; nt < 4; nt++) {
                uint32_t off = SW128((uint32_t)((b_row + nt * 8) * 128 + ks * 32 + b_kb));
                ldsm_x2(bh[nt], stb + SB_H + off);
                ldsm_x2(bl[nt], stb + SB_L + off);
            }
            #pragma unroll
            for (int mt = 0; mt < 4; mt++)
                #pragma unroll
                for (int nt = 0; nt < 4; nt++) {
                    mma16816(acc[mt][nt], ah[mt], bh[nt]);
                    mma16816(acc[mt][nt], ah[mt], bl[nt]);
                    mma16816(acc[mt][nt], al[mt], bh[nt]);
                }
        }
        __syncthreads();
    }
    #undef LOAD_STAGE

    // ---- epilogue ----
    #pragma unroll
    for (int mt = 0; mt < 4; mt++) {
        #pragma unroll
        for (int half = 0; half < 2; half++) {
            int gr = row0 + wm * 64 + mt * 16 + (lane >> 2) + half * 8;
            bool rowok = gr < M;
            float ps = 0.f, pd = 0.f;
            #pragma unroll
            for (int nt = 0; nt < 4; nt++) {
                int gc = col0 + wn * 32 + nt * 8 + (lane & 3) * 2;
                float v0 = acc[mt][nt][half * 2 + 0];
                float v1 = acc[mt][nt][half * 2 + 1];
                if (bias) { v0 += __ldg(bias + gc); v1 += __ldg(bias + gc + 1); }
                if (rowok) {
                    size_t base = (size_t)gr * F + gc;
                    if (out)
                        *reinterpret_cast<float2*>(out + base) = make_float2(v0, v1);
                    if (write_split) {
                        __nv_bfloat16 h0 = __float2bfloat16(v0);
                        __nv_bfloat16 h1 = __float2bfloat16(v1);
                        __nv_bfloat16 l0 = __float2bfloat16(v0 - __bfloat162float(h0));
                        __nv_bfloat16 l1 = __float2bfloat16(v1 - __bfloat162float(h1));
                        *reinterpret_cast<__nv_bfloat162*>(g_Ah + base) = __nv_bfloat162(h0, h1);
                        *reinterpret_cast<__nv_bfloat162*>(g_Al + base) = __nv_bfloat162(l0, l1);
                    }
                    if (a_src) {
                        ps += v0 * __ldg(a_src + gc) + v1 * __ldg(a_src + gc + 1);
                        pd += v0 * __ldg(a_dst + gc) + v1 * __ldg(a_dst + gc + 1);
                    }
                }
            }
            if (a_src) {
                ps += __shfl_xor_sync(0xffffffffu, ps, 1);
                ps += __shfl_xor_sync(0xffffffffu, ps, 2);
                pd += __shfl_xor_sync(0xffffffffu, pd, 1);
                pd += __shfl_xor_sync(0xffffffffu, pd, 2);
                if (rowok && (lane & 3) == 0) {
                    atomicAdd(&als[gr], ps);
                    atomicAdd(&ald[gr], pd);
                }
            }
        }
    }
}

// ---------------- GAT aggregation: warp per destination node ----------------
__global__ void aggregate_kernel(const float* __restrict__ hW,
                                 const float* __restrict__ bias,
                                 const float* __restrict__ als,
                                 const float* __restrict__ ald_arr,
                                 float* __restrict__ out, int write_split) {
    int node = (blockIdx.x * blockDim.x + threadIdx.x) >> 5;
    int lane = threadIdx.x & 31;
    if (node >= N_NODES) return;
    int beg = node * SLOT_CAP;
    int end = beg + g_deg[node];
    float ald = ald_arr[node];
    float m = -INFINITY;
    for (int j = beg + lane; j < end; j += 32) {
        float e = als[g_srcs[j]] + ald;
        e = (e > 0.f) ? e : NEG_SLOPE * e;
        m = fmaxf(m, e);
    }
    #pragma unroll
    for (int o = 16; o > 0; o >>= 1) m = fmaxf(m, __shfl_xor_sync(0xffffffffu, m, o));
    float s = 0.f;
    for (int j = beg + lane; j < end; j += 32) {
        float e = als[g_srcs[j]] + ald;
        e = (e > 0.f) ? e : NEG_SLOPE * e;
        s += __expf(e - m);
    }
    #pragma unroll
    for (int o = 16; o > 0; o >>= 1) s += __shfl_xor_sync(0xffffffffu, s, o);
    float inv = 1.f / (s + EPS_F);
    float4 acc0 = make_float4(0.f, 0.f, 0.f, 0.f);
    float4 acc1 = make_float4(0.f, 0.f, 0.f, 0.f);
    for (int j = beg; j < end; j++) {
        int src = g_srcs[j];
        float e = als[src] + ald;
        e = (e > 0.f) ? e : NEG_SLOPE * e;
        float w = __expf(e - m);
        const float4* hr = reinterpret_cast<const float4*>(hW + (size_t)src * F);
        float4 v0 = __ldg(hr + lane);
        float4 v1 = __ldg(hr + lane + 32);
        acc0.x = fmaf(w, v0.x, acc0.x); acc0.y = fmaf(w, v0.y, acc0.y);
        acc0.z = fmaf(w, v0.z, acc0.z); acc0.w = fmaf(w, v0.w, acc0.w);
        acc1.x = fmaf(w, v1.x, acc1.x); acc1.y = fmaf(w, v1.y, acc1.y);
        acc1.z = fmaf(w, v1.z, acc1.z); acc1.w = fmaf(w, v1.w, acc1.w);
    }
    const float4* brow = reinterpret_cast<const float4*>(bias);
    float4 b0 = __ldg(brow + lane);
    float4 b1 = __ldg(brow + lane + 32);
    float4 r0 = make_float4(acc0.x * inv + b0.x, acc0.y * inv + b0.y,
                            acc0.z * inv + b0.z, acc0.w * inv + b0.w);
    float4 r1 = make_float4(acc1.x * inv + b1.x, acc1.y * inv + b1.y,
                            acc1.z * inv + b1.z, acc1.w * inv + b1.w);
    if (out) {
        float4* orow = reinterpret_cast<float4*>(out + (size_t)node * F);
        orow[lane] = r0;
        orow[lane + 32] = r1;
    }
    if (write_split) {
        #pragma unroll
        for (int g = 0; g < 2; g++) {
            float4 r = g ? r1 : r0;
            size_t base = (size_t)node * F + (size_t)(lane + g * 32) * 4;
            __nv_bfloat16 h0 = __float2bfloat16(r.x), h1 = __float2bfloat16(r.y);
            __nv_bfloat16 h2 = __float2bfloat16(r.z), h3 = __float2bfloat16(r.w);
            __nv_bfloat16 l0 = __float2bfloat16(r.x - __bfloat162float(h0));
            __nv_bfloat16 l1 = __float2bfloat16(r.y - __bfloat162float(h1));
            __nv_bfloat16 l2 = __float2bfloat16(r.z - __bfloat162float(h2));
            __nv_bfloat16 l3 = __float2bfloat16(r.w - __bfloat162float(h3));
            *reinterpret_cast<__nv_bfloat162*>(g_Ah + base)     = __nv_bfloat162(h0, h1);
            *reinterpret_cast<__nv_bfloat162*>(g_Ah + base + 2) = __nv_bfloat162(h2, h3);
            *reinterpret_cast<__nv_bfloat162*>(g_Al + base)     = __nv_bfloat162(l0, l1);
            *reinterpret_cast<__nv_bfloat162*>(g_Al + base + 2) = __nv_bfloat162(l2, l3);
        }
    }
}

// ---------------- eval-edge dot products ----------------
__global__ void dot_kernel(const float* __restrict__ h,
                           const int* __restrict__ ei,
                           float* __restrict__ out) {
    int eid = (blockIdx.x * blockDim.x + threadIdx.x) >> 5;
    int lane = threadIdx.x & 31;
    if (eid >= E_EVAL) return;
    int a = ei[eid];
    int b = ei[E_EVAL + eid];
    const float4* ha = reinterpret_cast<const float4*>(h + (size_t)a * F);
    const float4* hb = reinterpret_cast<const float4*>(h + (size_t)b * F);
    float s = 0.f;
    #pragma unroll
    for (int k = 0; k < 2; k++) {
        float4 va = __ldg(ha + lane + k * 32);
        float4 vb = __ldg(hb + lane + k * 32);
        s = fmaf(va.x, vb.x, s);
        s = fmaf(va.y, vb.y, s);
        s = fmaf(va.z, vb.z, s);
        s = fmaf(va.w, vb.w, s);
    }
    #pragma unroll
    for (int o = 16; o > 0; o >>= 1) s += __shfl_xor_sync(0xffffffffu, s, o);
    if (lane == 0) out[eid] = s;
}

// ---------------- launch ----------------
extern "C" void kernel_launch(void* const* d_in, const int* in_sizes, int n_in,
                              void* d_out, int out_size) {
    const float* x       = (const float*)d_in[0];
    const int*   pos_ei  = (const int*)  d_in[1];
    const int*   ev_ei   = (const int*)  d_in[2];
    const float* Win_W   = (const float*)d_in[3];
    const float* Win_b   = (const float*)d_in[4];
    const float* W1      = (const float*)d_in[5];
    const float* a1_src  = (const float*)d_in[6];
    const float* a1_dst  = (const float*)d_in[7];
    const float* b1      = (const float*)d_in[8];
    const float* W2      = (const float*)d_in[9];
    const float* a2_src  = (const float*)d_in[10];
    const float* a2_dst  = (const float*)d_in[11];
    const float* b2      = (const float*)d_in[12];
    float* out = (float*)d_out;

    float *pA, *pB, *pAls1, *pAld1, *pAls2, *pAld2;
    __nv_bfloat16 *pWh, *pWl;
    cudaGetSymbolAddress((void**)&pA, g_bufA);
    cudaGetSymbolAddress((void**)&pB, g_bufB);
    cudaGetSymbolAddress((void**)&pAls1, g_als1);
    cudaGetSymbolAddress((void**)&pAld1, g_ald1);
    cudaGetSymbolAddress((void**)&pAls2, g_als2);
    cudaGetSymbolAddress((void**)&pAld2, g_ald2);
    cudaGetSymbolAddress((void**)&pWh, g_Wh);
    cudaGetSymbolAddress((void**)&pWl, g_Wl);

    cudaFuncSetAttribute(gemm_mma_kernel,
                         cudaFuncAttributeMaxDynamicSharedMemorySize, SMEM_MMA);

    const dim3 ggrid(2, (N_NODES + 127) / 128);
    const int split_blocks = (M4_A + 3 * F * F + 255) / 256;
    const int warps_blocks_n = (N_NODES * 32 + 255) / 256;

    prep_kernel<<<(N_NODES + 255) / 256, 256>>>();
    scatter_kernel<<<(E_Q + 255) / 256, 256>>>(pos_ei);
    split_all_kernel<<<split_blocks, 256>>>(x, Win_W, W1, W2);

    // gemm0: h0 = x @ Win_W + Win_b  -> bf16 split only
    gemm_mma_kernel<<<ggrid, 256, SMEM_MMA>>>(
        pWh + 0 * F * F, pWl + 0 * F * F, Win_b,
        nullptr, nullptr, nullptr, nullptr, nullptr, 1, N_NODES);

    // gemm1: hW1 = h0 @ W1 -> fp32 pA + fused al1
    gemm_mma_kernel<<<ggrid, 256, SMEM_MMA>>>(
        pWh + 1 * F * F, pWl + 1 * F * F, nullptr,
        a1_src, a1_dst, pAls1, pAld1, pA, 0, N_NODES);
    // aggregate layer1 -> bf16 split for gemm2 (no fp32 needed)
    aggregate_kernel<<<warps_blocks_n, 256>>>(pA, b1, pAls1, pAld1, nullptr, 1);

    // gemm2: hW2 = h1 @ W2 -> fp32 pA + fused al2
    gemm_mma_kernel<<<ggrid, 256, SMEM_MMA>>>(
        pWh + 2 * F * F, pWl + 2 * F * F, nullptr,
        a2_src, a2_dst, pAls2, pAld2, pA, 0, N_NODES);
    // aggregate layer2 -> fp32 pB (distinct buffer; no in-place race)
    aggregate_kernel<<<warps_blocks_n, 256>>>(pA, b2, pAls2, pAld2, pB, 0);

    // eval logits
    dot_kernel<<<(E_EVAL * 32 + 255) / 256, 256>>>(pB, ev_ei, out);
}

// round 5
// speedup vs baseline: 1.7640x; 1.1674x over previous
#include <cuda_runtime.h>
#include <cuda_bf16.h>
#include <cstdint>
#include <math.h>

#define N_NODES 10000
#define F 256
#define E_POS 320000
#define E_TOT 330000
#define E_EVAL 100000
#define NEG_SLOPE 0.2f
#define EPS_F 1e-16f
#define SLOT_CAP 128

// ---------------- scratch (device globals; allocation-free) ----------------
__device__ float g_bufA[N_NODES * F];     // gemm fp32 out
__device__ float g_bufB[N_NODES * F];     // aggregate2 out (final h)
__device__ float g_als1[N_NODES];
__device__ float g_ald1[N_NODES];
__device__ float g_als2[N_NODES];
__device__ float g_ald2[N_NODES];
__device__ int   g_deg[N_NODES];
__device__ int   g_srcs[N_NODES * SLOT_CAP];
__device__ __nv_bfloat16 g_Ah[N_NODES * F];
__device__ __nv_bfloat16 g_Al[N_NODES * F];
__device__ __nv_bfloat16 g_Wh[3][F * F];  // transposed [n][k]
__device__ __nv_bfloat16 g_Wl[3][F * F];

#define SW128(o) ((o) ^ (((o) >> 3) & 0x70))

__device__ __forceinline__ uint32_t smem_to_u32(const void* p) {
    uint32_t a;
    asm("{ .reg .u64 t; cvta.to.shared.u64 t, %1; cvt.u32.u64 %0, t; }"
        : "=r"(a) : "l"(p));
    return a;
}
__device__ __forceinline__ void ldsm_x4(uint32_t* r, uint32_t addr) {
    asm volatile("ldmatrix.sync.aligned.m8n8.x4.shared.b16 {%0,%1,%2,%3}, [%4];"
        : "=r"(r[0]), "=r"(r[1]), "=r"(r[2]), "=r"(r[3]) : "r"(addr));
}
__device__ __forceinline__ void mma16816(float* c, const uint32_t* a, const uint32_t* b) {
    asm volatile(
        "mma.sync.aligned.m16n8k16.row.col.f32.bf16.bf16.f32 "
        "{%0,%1,%2,%3}, {%4,%5,%6,%7}, {%8,%9}, {%0,%1,%2,%3};"
        : "+f"(c[0]), "+f"(c[1]), "+f"(c[2]), "+f"(c[3])
        : "r"(a[0]), "r"(a[1]), "r"(a[2]), "r"(a[3]), "r"(b[0]), "r"(b[1]));
}
__device__ __forceinline__ void cp_async16(uint32_t saddr, const void* g, bool valid) {
    int sz = valid ? 16 : 0;
    asm volatile("cp.async.cg.shared.global [%0], [%1], 16, %2;"
        :: "r"(saddr), "l"(g), "r"(sz) : "memory");
}
#define CP_COMMIT() asm volatile("cp.async.commit_group;" ::: "memory")
#define CP_WAIT(n)  asm volatile("cp.async.wait_group %0;" :: "n"(n) : "memory")

// ---------------- prep / CSR ----------------
__global__ void prep_kernel() {
    int i = blockIdx.x * blockDim.x + threadIdx.x;
    if (i < N_NODES) {
        g_deg[i] = 0;
        g_als1[i] = 0.f; g_ald1[i] = 0.f;
        g_als2[i] = 0.f; g_ald2[i] = 0.f;
    }
}

#define E_Q (E_TOT / 4)   // 82500
__global__ void scatter_kernel(const int* __restrict__ pos_ei) {
    int gid = blockIdx.x * blockDim.x + threadIdx.x;
    if (gid >= E_Q) return;
    #pragma unroll
    for (int q = 0; q < 4; q++) {
        int e = gid + q * E_Q;
        int src, dst;
        if (e < E_POS) { src = __ldg(pos_ei + e); dst = __ldg(pos_ei + E_POS + e); }
        else           { src = e - E_POS; dst = src; }
        int pos = atomicAdd(&g_deg[dst], 1);
        if (pos < SLOT_CAP) g_srcs[dst * SLOT_CAP + pos] = src;
    }
}

// ---------------- split x + all 3 weight matrices ----------------
#define M4_A (N_NODES * F / 4)
__global__ void split_all_kernel(const float* __restrict__ x,
                                 const float* __restrict__ W0,
                                 const float* __restrict__ W1,
                                 const float* __restrict__ W2) {
    int idx = blockIdx.x * blockDim.x + threadIdx.x;
    if (idx < M4_A) {
        float4 v = reinterpret_cast<const float4*>(x)[idx];
        __nv_bfloat16 h0 = __float2bfloat16(v.x), h1 = __float2bfloat16(v.y);
        __nv_bfloat16 h2 = __float2bfloat16(v.z), h3 = __float2bfloat16(v.w);
        __nv_bfloat16 l0 = __float2bfloat16(v.x - __bfloat162float(h0));
        __nv_bfloat16 l1 = __float2bfloat16(v.y - __bfloat162float(h1));
        __nv_bfloat16 l2 = __float2bfloat16(v.z - __bfloat162float(h2));
        __nv_bfloat16 l3 = __float2bfloat16(v.w - __bfloat162float(h3));
        __nv_bfloat162* ph = reinterpret_cast<__nv_bfloat162*>(g_Ah);
        __nv_bfloat162* pl = reinterpret_cast<__nv_bfloat162*>(g_Al);
        ph[idx * 2]     = __nv_bfloat162(h0, h1);
        ph[idx * 2 + 1] = __nv_bfloat162(h2, h3);
        pl[idx * 2]     = __nv_bfloat162(l0, l1);
        pl[idx * 2 + 1] = __nv_bfloat162(l2, l3);
    } else {
        int i2 = idx - M4_A;
        if (i2 < 3 * F * F) {
            int w = i2 >> 16;
            int j = i2 & 65535;
            int k = j >> 8, n = j & 255;
            const float* W = (w == 0) ? W0 : (w == 1) ? W1 : W2;
            float v = __ldg(W + j);     // W[k][n]
            __nv_bfloat16 h = __float2bfloat16(v);
            __nv_bfloat16 l = __float2bfloat16(v - __bfloat162float(h));
            g_Wh[w][n * F + k] = h;     // transposed
            g_Wl[w][n * F + k] = l;
        }
    }
}

// ---------------- pipelined HMMA GEMM ----------------
// BM=64 BN=128 BK=64, 256 threads, 8 warps (2m x 4n), warp tile 32x32
// 2 CTAs/SM (96KB smem, <=128 regs)
#define SA_H 0
#define SA_L 8192
#define SB_H 16384
#define SB_L 32768
#define STAGE_BYTES 49152
#define SMEM_MMA (2 * STAGE_BYTES + 1024)

__global__ __launch_bounds__(256, 2) void gemm_mma_kernel(
    const __nv_bfloat16* __restrict__ Bh, const __nv_bfloat16* __restrict__ Bl,
    const float* __restrict__ bias,
    const float* __restrict__ a_src, const float* __restrict__ a_dst,
    float* __restrict__ als, float* __restrict__ ald,
    float* __restrict__ out, int write_split, int M) {
    extern __shared__ char dsmem[];
    const int tid = threadIdx.x;
    const int wid = tid >> 5;
    const int lane = tid & 31;
    const int wm = wid >> 2;          // 0..1  (32-row slice)
    const int wn = wid & 3;           // 0..3  (32-col slice)
    const int row0 = blockIdx.y * 64;
    const int col0 = blockIdx.x * 128;

    uint32_t dsb = smem_to_u32(dsmem);
    uint32_t sb = (dsb + 1023) & ~1023u;

    float acc[2][4][4] = {};          // [mt][n8][4]

    // A fragment lane addressing (ldsm_x4 m16k16)
    const int a_row = wm * 32 + (lane & 15);
    const int a_kb  = (lane >> 4) * 16;
    // B fragment lane addressing (ldsm_x4 -> two n8k16 fragments)
    const int b_row = wn * 32 + (lane & 7) + ((lane >> 4) & 1) * 8;
    const int b_kb  = ((lane >> 3) & 1) * 16;

    const __nv_bfloat16* opsA[2] = { g_Ah, g_Al };
    const __nv_bfloat16* opsB[2] = { Bh, Bl };
    const int boffA[2] = { SA_H, SA_L };
    const int boffB[2] = { SB_H, SB_L };

    const int lr = tid >> 3;          // 0..31
    const int lj = tid & 7;           // 16B chunk in row

    #define LOAD_STAGE(cc, ss) do {                                              \
        uint32_t stb = sb + (ss) * STAGE_BYTES;                                   \
        _Pragma("unroll")                                                         \
        for (int t = 0; t < 2; t++) {                                             \
            _Pragma("unroll")                                                     \
            for (int it = 0; it < 2; it++) {                                      \
                int r = lr + it * 32;                                             \
                int grow = row0 + r;                                              \
                uint32_t off = SW128((uint32_t)(r * 128 + lj * 16));              \
                cp_async16(stb + boffA[t] + off,                                  \
                           opsA[t] + (size_t)grow * F + (cc) * 64 + lj * 8,       \
                           grow < M);                                             \
            }                                                                     \
        }                                                                         \
        _Pragma("unroll")                                                         \
        for (int t = 0; t < 2; t++) {                                             \
            _Pragma("unroll")                                                     \
            for (int it = 0; it < 4; it++) {                                      \
                int r = lr + it * 32;                                             \
                uint32_t off = SW128((uint32_t)(r * 128 + lj * 16));              \
                cp_async16(stb + boffB[t] + off,                                  \
                           opsB[t] + (size_t)(col0 + r) * F + (cc) * 64 + lj * 8, \
                           true);                                                 \
            }                                                                     \
        }                                                                         \
        CP_COMMIT();                                                              \
    } while (0)

    LOAD_STAGE(0, 0);

    #pragma unroll
    for (int c = 0; c < 4; c++) {
        if (c + 1 < 4) {
            LOAD_STAGE(c + 1, (c + 1) & 1);
            CP_WAIT(1);
        } else {
            CP_WAIT(0);
        }
        __syncthreads();
        uint32_t stb = sb + (c & 1) * STAGE_BYTES;
        #pragma unroll
        for (int ks = 0; ks < 4; ks++) {
            uint32_t ah[2][4], al[2][4];          // [mt][4]
            uint32_t bh[2][4], bl[2][4];          // [ntp][4] -> 2 n8 frags each
            #pragma unroll
            for (int mt = 0; mt < 2; mt++) {
                uint32_t off = SW128((uint32_t)((a_row + mt * 16) * 128 + ks * 32 + a_kb));
                ldsm_x4(ah[mt], stb + SA_H + off);
                ldsm_x4(al[mt], stb + SA_L + off);
            }
            #pragma unroll
            for (int ntp = 0; ntp < 2; ntp++) {
                uint32_t off = SW128((uint32_t)((b_row + ntp * 16) * 128 + ks * 32 + b_kb));
                ldsm_x4(bh[ntp], stb + SB_H + off);
                ldsm_x4(bl[ntp], stb + SB_L + off);
            }
            #pragma unroll
            for (int mt = 0; mt < 2; mt++)
                #pragma unroll
                for (int n8 = 0; n8 < 4; n8++) {
                    const uint32_t* bhf = &bh[n8 >> 1][(n8 & 1) * 2];
                    const uint32_t* blf = &bl[n8 >> 1][(n8 & 1) * 2];
                    mma16816(acc[mt][n8], ah[mt], bhf);
                    mma16816(acc[mt][n8], ah[mt], blf);
                    mma16816(acc[mt][n8], al[mt], bhf);
                }
        }
        __syncthreads();
    }
    #undef LOAD_STAGE

    // ---- epilogue ----
    #pragma unroll
    for (int mt = 0; mt < 2; mt++) {
        #pragma unroll
        for (int half = 0; half < 2; half++) {
            int gr = row0 + wm * 32 + mt * 16 + (lane >> 2) + half * 8;
            bool rowok = gr < M;
            float ps = 0.f, pd = 0.f;
            #pragma unroll
            for (int n8 = 0; n8 < 4; n8++) {
                int gc = col0 + wn * 32 + n8 * 8 + (lane & 3) * 2;
                float v0 = acc[mt][n8][half * 2 + 0];
                float v1 = acc[mt][n8][half * 2 + 1];
                if (bias) { v0 += __ldg(bias + gc); v1 += __ldg(bias + gc + 1); }
                if (rowok) {
                    size_t base = (size_t)gr * F + gc;
                    if (out)
                        *reinterpret_cast<float2*>(out + base) = make_float2(v0, v1);
                    if (write_split) {
                        __nv_bfloat16 h0 = __float2bfloat16(v0);
                        __nv_bfloat16 h1 = __float2bfloat16(v1);
                        __nv_bfloat16 l0 = __float2bfloat16(v0 - __bfloat162float(h0));
                        __nv_bfloat16 l1 = __float2bfloat16(v1 - __bfloat162float(h1));
                        *reinterpret_cast<__nv_bfloat162*>(g_Ah + base) = __nv_bfloat162(h0, h1);
                        *reinterpret_cast<__nv_bfloat162*>(g_Al + base) = __nv_bfloat162(l0, l1);
                    }
                    if (a_src) {
                        ps += v0 * __ldg(a_src + gc) + v1 * __ldg(a_src + gc + 1);
                        pd += v0 * __ldg(a_dst + gc) + v1 * __ldg(a_dst + gc + 1);
                    }
                }
            }
            if (a_src) {
                ps += __shfl_xor_sync(0xffffffffu, ps, 1);
                ps += __shfl_xor_sync(0xffffffffu, ps, 2);
                pd += __shfl_xor_sync(0xffffffffu, pd, 1);
                pd += __shfl_xor_sync(0xffffffffu, pd, 2);
                if (rowok && (lane & 3) == 0) {
                    atomicAdd(&als[gr], ps);
                    atomicAdd(&ald[gr], pd);
                }
            }
        }
    }
}

// ---------------- GAT aggregation: warp per destination node ----------------
__global__ void aggregate_kernel(const float* __restrict__ hW,
                                 const float* __restrict__ bias,
                                 const float* __restrict__ als,
                                 const float* __restrict__ ald_arr,
                                 float* __restrict__ out, int write_split) {
    int node = (blockIdx.x * blockDim.x + threadIdx.x) >> 5;
    int lane = threadIdx.x & 31;
    if (node >= N_NODES) return;
    int beg = node * SLOT_CAP;
    int end = beg + g_deg[node];
    float ald = ald_arr[node];
    float m = -INFINITY;
    for (int j = beg + lane; j < end; j += 32) {
        float e = als[g_srcs[j]] + ald;
        e = (e > 0.f) ? e : NEG_SLOPE * e;
        m = fmaxf(m, e);
    }
    #pragma unroll
    for (int o = 16; o > 0; o >>= 1) m = fmaxf(m, __shfl_xor_sync(0xffffffffu, m, o));
    float s = 0.f;
    for (int j = beg + lane; j < end; j += 32) {
        float e = als[g_srcs[j]] + ald;
        e = (e > 0.f) ? e : NEG_SLOPE * e;
        s += __expf(e - m);
    }
    #pragma unroll
    for (int o = 16; o > 0; o >>= 1) s += __shfl_xor_sync(0xffffffffu, s, o);
    float inv = 1.f / (s + EPS_F);
    float4 acc0 = make_float4(0.f, 0.f, 0.f, 0.f);
    float4 acc1 = make_float4(0.f, 0.f, 0.f, 0.f);
    for (int j = beg; j < end; j++) {
        int src = g_srcs[j];
        float e = als[src] + ald;
        e = (e > 0.f) ? e : NEG_SLOPE * e;
        float w = __expf(e - m);
        const float4* hr = reinterpret_cast<const float4*>(hW + (size_t)src * F);
        float4 v0 = __ldg(hr + lane);
        float4 v1 = __ldg(hr + lane + 32);
        acc0.x = fmaf(w, v0.x, acc0.x); acc0.y = fmaf(w, v0.y, acc0.y);
        acc0.z = fmaf(w, v0.z, acc0.z); acc0.w = fmaf(w, v0.w, acc0.w);
        acc1.x = fmaf(w, v1.x, acc1.x); acc1.y = fmaf(w, v1.y, acc1.y);
        acc1.z = fmaf(w, v1.z, acc1.z); acc1.w = fmaf(w, v1.w, acc1.w);
    }
    const float4* brow = reinterpret_cast<const float4*>(bias);
    float4 b0 = __ldg(brow + lane);
    float4 b1 = __ldg(brow + lane + 32);
    float4 r0 = make_float4(acc0.x * inv + b0.x, acc0.y * inv + b0.y,
                            acc0.z * inv + b0.z, acc0.w * inv + b0.w);
    float4 r1 = make_float4(acc1.x * inv + b1.x, acc1.y * inv + b1.y,
                            acc1.z * inv + b1.z, acc1.w * inv + b1.w);
    if (out) {
        float4* orow = reinterpret_cast<float4*>(out + (size_t)node * F);
        orow[lane] = r0;
        orow[lane + 32] = r1;
    }
    if (write_split) {
        #pragma unroll
        for (int g = 0; g < 2; g++) {
            float4 r = g ? r1 : r0;
            size_t base = (size_t)node * F + (size_t)(lane + g * 32) * 4;
            __nv_bfloat16 h0 = __float2bfloat16(r.x), h1 = __float2bfloat16(r.y);
            __nv_bfloat16 h2 = __float2bfloat16(r.z), h3 = __float2bfloat16(r.w);
            __nv_bfloat16 l0 = __float2bfloat16(r.x - __bfloat162float(h0));
            __nv_bfloat16 l1 = __float2bfloat16(r.y - __bfloat162float(h1));
            __nv_bfloat16 l2 = __float2bfloat16(r.z - __bfloat162float(h2));
            __nv_bfloat16 l3 = __float2bfloat16(r.w - __bfloat162float(h3));
            *reinterpret_cast<__nv_bfloat162*>(g_Ah + base)     = __nv_bfloat162(h0, h1);
            *reinterpret_cast<__nv_bfloat162*>(g_Ah + base + 2) = __nv_bfloat162(h2, h3);
            *reinterpret_cast<__nv_bfloat162*>(g_Al + base)     = __nv_bfloat162(l0, l1);
            *reinterpret_cast<__nv_bfloat162*>(g_Al + base + 2) = __nv_bfloat162(l2, l3);
        }
    }
}

// ---------------- eval-edge dot products ----------------
__global__ void dot_kernel(const float* __restrict__ h,
                           const int* __restrict__ ei,
                           float* __restrict__ out) {
    int eid = (blockIdx.x * blockDim.x + threadIdx.x) >> 5;
    int lane = threadIdx.x & 31;
    if (eid >= E_EVAL) return;
    int a = ei[eid];
    int b = ei[E_EVAL + eid];
    const float4* ha = reinterpret_cast<const float4*>(h + (size_t)a * F);
    const float4* hb = reinterpret_cast<const float4*>(h + (size_t)b * F);
    float s = 0.f;
    #pragma unroll
    for (int k = 0; k < 2; k++) {
        float4 va = __ldg(ha + lane + k * 32);
        float4 vb = __ldg(hb + lane + k * 32);
        s = fmaf(va.x, vb.x, s);
        s = fmaf(va.y, vb.y, s);
        s = fmaf(va.z, vb.z, s);
        s = fmaf(va.w, vb.w, s);
    }
    #pragma unroll
    for (int o = 16; o > 0; o >>= 1) s += __shfl_xor_sync(0xffffffffu, s, o);
    if (lane == 0) out[eid] = s;
}

// ---------------- launch ----------------
extern "C" void kernel_launch(void* const* d_in, const int* in_sizes, int n_in,
                              void* d_out, int out_size) {
    const float* x       = (const float*)d_in[0];
    const int*   pos_ei  = (const int*)  d_in[1];
    const int*   ev_ei   = (const int*)  d_in[2];
    const float* Win_W   = (const float*)d_in[3];
    const float* Win_b   = (const float*)d_in[4];
    const float* W1      = (const float*)d_in[5];
    const float* a1_src  = (const float*)d_in[6];
    const float* a1_dst  = (const float*)d_in[7];
    const float* b1      = (const float*)d_in[8];
    const float* W2      = (const float*)d_in[9];
    const float* a2_src  = (const float*)d_in[10];
    const float* a2_dst  = (const float*)d_in[11];
    const float* b2      = (const float*)d_in[12];
    float* out = (float*)d_out;

    float *pA, *pB, *pAls1, *pAld1, *pAls2, *pAld2;
    __nv_bfloat16 *pWh, *pWl;
    cudaGetSymbolAddress((void**)&pA, g_bufA);
    cudaGetSymbolAddress((void**)&pB, g_bufB);
    cudaGetSymbolAddress((void**)&pAls1, g_als1);
    cudaGetSymbolAddress((void**)&pAld1, g_ald1);
    cudaGetSymbolAddress((void**)&pAls2, g_als2);
    cudaGetSymbolAddress((void**)&pAld2, g_ald2);
    cudaGetSymbolAddress((void**)&pWh, g_Wh);
    cudaGetSymbolAddress((void**)&pWl, g_Wl);

    cudaFuncSetAttribute(gemm_mma_kernel,
                         cudaFuncAttributeMaxDynamicSharedMemorySize, SMEM_MMA);

    const dim3 ggrid(2, (N_NODES + 63) / 64);
    const int split_blocks = (M4_A + 3 * F * F + 255) / 256;
    const int warps_blocks_n = (N_NODES * 32 + 255) / 256;

    prep_kernel<<<(N_NODES + 255) / 256, 256>>>();
    scatter_kernel<<<(E_Q + 255) / 256, 256>>>(pos_ei);
    split_all_kernel<<<split_blocks, 256>>>(x, Win_W, W1, W2);

    // gemm0: h0 = x @ Win_W + Win_b  -> bf16 split only
    gemm_mma_kernel<<<ggrid, 256, SMEM_MMA>>>(
        pWh + 0 * F * F, pWl + 0 * F * F, Win_b,
        nullptr, nullptr, nullptr, nullptr, nullptr, 1, N_NODES);

    // gemm1: hW1 = h0 @ W1 -> fp32 pA + fused al1
    gemm_mma_kernel<<<ggrid, 256, SMEM_MMA>>>(
        pWh + 1 * F * F, pWl + 1 * F * F, nullptr,
        a1_src, a1_dst, pAls1, pAld1, pA, 0, N_NODES);
    aggregate_kernel<<<warps_blocks_n, 256>>>(pA, b1, pAls1, pAld1, nullptr, 1);

    // gemm2: hW2 = h1 @ W2 -> fp32 pA + fused al2
    gemm_mma_kernel<<<ggrid, 256, SMEM_MMA>>>(
        pWh + 2 * F * F, pWl + 2 * F * F, nullptr,
        a2_src, a2_dst, pAls2, pAld2, pA, 0, N_NODES);
    aggregate_kernel<<<warps_blocks_n, 256>>>(pA, b2, pAls2, pAld2, pB, 0);

    // eval logits
    dot_kernel<<<(E_EVAL * 32 + 255) / 256, 256>>>(pB, ev_ei, out);
}